// round 9
// baseline (speedup 1.0000x reference)
#include <cuda_runtime.h>

#define NN (1 << 20)   // rows
#define DD 32          // dim
#define QQ 4           // stages
#define KK 256         // codewords per stage

static constexpr int THREADS = 256;
static constexpr int ROWS_PER_THREAD = 2;
static constexpr int ROWS_PER_BLOCK = THREADS * ROWS_PER_THREAD;  // 512
static constexpr int GRID = NN / ROWS_PER_BLOCK;                  // 2048

// Deterministic loss scratch (no atomics): one double per block.
__device__ double g_partials[GRID];

typedef unsigned long long u64;

__device__ __forceinline__ u64 fma2(u64 a, u64 b, u64 c) {
    u64 d;
    asm("fma.rn.f32x2 %0, %1, %2, %3;" : "=l"(d) : "l"(a), "l"(b), "l"(c));
    return d;
}
__device__ __forceinline__ u64 add2(u64 a, u64 b) {
    u64 d;
    asm("add.rn.f32x2 %0, %1, %2;" : "=l"(d) : "l"(a), "l"(b));
    return d;
}
__device__ __forceinline__ float2 unpack2(u64 v) {
    float2 f;
    asm("mov.b64 {%0, %1}, %2;" : "=f"(f.x), "=f"(f.y) : "l"(v));
    return f;
}
__device__ __forceinline__ u64 pack2(float x, float y) {
    u64 v;
    asm("mov.b64 %0, {%1, %2};" : "=l"(v) : "f"(x), "f"(y));
    return v;
}
__device__ __forceinline__ u64 sub2(u64 a, u64 b) {
    float2 fa = unpack2(a), fb = unpack2(b);
    return pack2(__fsub_rn(fa.x, fb.x), __fsub_rn(fa.y, fb.y));
}
__device__ __forceinline__ u64 neg2(u64 a) {       // exact sign flip, both lanes
    return a ^ 0x8000000080000000ULL;
}

// DECISION ARITHMETIC (bit-exact to the verified R8 pass): g accumulated as a
// sequential ascending chain of SEPARATE mul/add. Codebook in smem is NEGATED,
// so we accumulate -g; all negations are exact and sign-symmetric rounding
// makes every intermediate the exact negation of the original chain.
__device__ __noinline__ int sep_argmin(const u64* r, int lane, const u64* s_ncb2,
                                       const float* s_ee, float rr)
{
    float rs[DD];
    #pragma unroll
    for (int j = 0; j < DD; j++) {
        float2 f = unpack2(r[j]);
        rs[j] = lane ? f.y : f.x;
    }
    float dmin = 3.4e38f;
    int best = 0;
    for (int k = 0; k < KK; k++) {
        const u64* cw = s_ncb2 + (size_t)k * DD;
        float accn = 0.0f;   // = -g, bit-exact negation of original chain
        #pragma unroll
        for (int j = 0; j < DD; j++)
            accn = __fadd_rn(accn, __fmul_rn(rs[j], unpack2(cw[j]).x));
        // d = fl( fl(rr - 2g) + ee ) = fl( fl(rr + 2*accn) + ee )
        float d = __fadd_rn(__fadd_rn(rr, __fmul_rn(2.0f, accn)), s_ee[k]);
        if (d < dmin) { dmin = d; best = k; }
    }
    return best;
}

__global__ __launch_bounds__(THREADS, 2)
void rvq_kernel(const float* __restrict__ x,
                const float* __restrict__ codebooks,
                float* __restrict__ out)
{
    extern __shared__ u64 smem_raw[];
    u64*  s_ncb2 = smem_raw;                        // KK*DD u64: (-e, -e) duplicated
    u64*  s_eh2  = smem_raw + KK * DD;              // KK u64: (ee/2, ee/2)
    float* s_ee  = (float*)(smem_raw + KK * DD + KK);  // KK floats: raw ||e||^2

    const int tid = threadIdx.x;
    const size_t row0 = (size_t)blockIdx.x * ROWS_PER_BLOCK + (size_t)tid * 2;

    // Residuals for 2 rows packed across f32x2 lanes: r[j] = (row0[j], row1[j]).
    u64 r[DD];
    {
        const float4* p0 = (const float4*)(x + row0 * DD);
        const float4* p1 = (const float4*)(x + (row0 + 1) * DD);
        #pragma unroll
        for (int j = 0; j < 8; j++) {
            float4 a = p0[j];
            float4 b = p1[j];
            r[4 * j + 0] = pack2(a.x, b.x);
            r[4 * j + 1] = pack2(a.y, b.y);
            r[4 * j + 2] = pack2(a.z, b.z);
            r[4 * j + 3] = pack2(a.w, b.w);
        }
    }

    float* oind = out + (size_t)NN * DD + 1;   // indices region (after x_q and loss)
    double loss_sum = 0.0;

    for (int q = 0; q < QQ; q++) {
        __syncthreads();  // previous stage done reading smem
        // Cooperative: thread k loads codeword k; stores (-e,-e); computes ee
        // (sequential ascending, separate mul/add -- the rescan's exact value).
        {
            const float* src = codebooks + ((size_t)q * KK + tid) * DD;
            float acc = 0.0f;
            #pragma unroll
            for (int j = 0; j < DD; j++) {
                float e = src[j];
                float ne = -e;
                s_ncb2[tid * DD + j] = pack2(ne, ne);
                acc = __fadd_rn(acc, __fmul_rn(e, e));
            }
            s_ee[tid] = acc;
            float eh = acc * 0.5f;               // exact (x0.5)
            s_eh2[tid] = pack2(eh, eh);
        }
        __syncthreads();

        // rr per row (decision arithmetic input): sequential, separate mul/add.
        float rr0, rr1;
        {
            u64 acc2 = 0ull;
            #pragma unroll
            for (int j = 0; j < DD; j++) {
                float2 f = unpack2(r[j]);
                float2 a = unpack2(acc2);
                acc2 = pack2(__fadd_rn(a.x, __fmul_rn(f.x, f.x)),
                             __fadd_rn(a.y, __fmul_rn(f.y, f.y)));
            }
            float2 f = unpack2(acc2);
            rr0 = f.x; rr1 = f.y;
        }

        // SCREEN: s_k = ee/2 - g_k  (same order as d_k; rr drops out).
        // Dual fused-FMA2 chains; branchless min/second-min/index tracking.
        const float SAFE_GAP_S = 1e-3f;   // == 2e-3 in d units, >= 3x divergence bound
        float dmin0 = 3.4e38f, dmin1 = 3.4e38f;
        float dsec0 = 3.4e38f, dsec1 = 3.4e38f;
        int best0 = 0, best1 = 0;
        for (int k = 0; k < KK; k++) {
            const ulonglong2* cw = (const ulonglong2*)(s_ncb2 + (size_t)k * DD);
            u64 a = s_eh2[k];    // chain A starts at (eh, eh)
            u64 b = 0ull;        // chain B starts at 0
            #pragma unroll
            for (int jj = 0; jj < 8; jj++) {
                ulonglong2 ea = cw[jj];        // dims 2jj, 2jj+1   (negated e)
                ulonglong2 eb = cw[jj + 8];    // dims 16+2jj, 17+2jj
                a = fma2(r[2 * jj],      ea.x, a);
                b = fma2(r[16 + 2 * jj], eb.x, b);
                a = fma2(r[2 * jj + 1],  ea.y, a);
                b = fma2(r[17 + 2 * jj], eb.y, b);
            }
            float2 s = unpack2(add2(a, b));
            // branchless track (FSETP + FSEL + 2xFMNMX + SEL per row)
            bool p0 = s.x < dmin0;
            float c0 = p0 ? dmin0 : s.x;
            dsec0 = fminf(dsec0, c0);
            dmin0 = fminf(dmin0, s.x);
            best0 = p0 ? k : best0;
            bool p1 = s.y < dmin1;
            float c1 = p1 ? dmin1 : s.y;
            dsec1 = fminf(dsec1, c1);
            dmin1 = fminf(dmin1, s.y);
            best1 = p1 ? k : best1;
        }

        // Contested rows (tiny fraction): exact separate-op re-decision.
        if (dsec0 - dmin0 < SAFE_GAP_S) best0 = sep_argmin(r, 0, s_ncb2, s_ee, rr0);
        if (dsec1 - dmin1 < SAFE_GAP_S) best1 = sep_argmin(r, 1, s_ncb2, s_ee, rr1);

        // Emit indices (as float) for this stage.
        oind[row0 * QQ + q]       = (float)best0;
        oind[(row0 + 1) * QQ + q] = (float)best1;

        // Residual update + loss (bit-identical to verified pass):
        //   t = fl(e - r) = -fl(ne + r);  xres = r + t;  r = r - xres
        const u64* e0 = s_ncb2 + (size_t)best0 * DD;
        const u64* e1 = s_ncb2 + (size_t)best1 * DD;
        u64 lacc = 0ull;
        #pragma unroll
        for (int j = 0; j < DD; j++) {
            float ne0 = unpack2(e0[j]).x;
            float ne1 = unpack2(e1[j]).x;
            u64 ne2 = pack2(ne0, ne1);
            u64 t2 = neg2(add2(ne2, r[j]));      // exact: -fl(ne+r) == fl(e-r)
            lacc = fma2(t2, t2, lacc);
            u64 xres2 = add2(r[j], t2);
            r[j] = sub2(r[j], xres2);
        }
        float2 lf = unpack2(lacc);
        loss_sum += (double)lf.x + (double)lf.y;
    }

    // x_q = x - r_final.
    {
        const float4* p0 = (const float4*)(x + row0 * DD);
        const float4* p1 = (const float4*)(x + (row0 + 1) * DD);
        float4* o0 = (float4*)(out + row0 * DD);
        float4* o1 = (float4*)(out + (row0 + 1) * DD);
        #pragma unroll
        for (int j = 0; j < 8; j++) {
            float4 a = p0[j];
            float4 b = p1[j];
            float2 r0 = unpack2(r[4 * j + 0]);
            float2 r1 = unpack2(r[4 * j + 1]);
            float2 r2 = unpack2(r[4 * j + 2]);
            float2 r3 = unpack2(r[4 * j + 3]);
            float4 w, z;
            w.x = __fsub_rn(a.x, r0.x); z.x = __fsub_rn(b.x, r0.y);
            w.y = __fsub_rn(a.y, r1.x); z.y = __fsub_rn(b.y, r1.y);
            w.z = __fsub_rn(a.z, r2.x); z.z = __fsub_rn(b.z, r2.y);
            w.w = __fsub_rn(a.w, r3.x); z.w = __fsub_rn(b.w, r3.y);
            o0[j] = w;
            o1[j] = z;
        }
    }

    // Deterministic per-block loss partial.
    double s = loss_sum;
    #pragma unroll
    for (int off = 16; off > 0; off >>= 1)
        s += __shfl_down_sync(0xffffffffu, s, off);
    __shared__ double wsum[THREADS / 32];
    if ((tid & 31) == 0) wsum[tid >> 5] = s;
    __syncthreads();
    if (tid == 0) {
        double b = 0.0;
        #pragma unroll
        for (int w = 0; w < THREADS / 32; w++) b += wsum[w];
        g_partials[blockIdx.x] = b;
    }
}

__global__ void rvq_finalize(float* __restrict__ out)
{
    __shared__ double sh[256];
    double s = 0.0;
    for (int i = threadIdx.x; i < GRID; i += 256) s += g_partials[i];  // fixed order
    sh[threadIdx.x] = s;
    __syncthreads();
    for (int stride = 128; stride > 0; stride >>= 1) {
        if (threadIdx.x < stride) sh[threadIdx.x] += sh[threadIdx.x + stride];
        __syncthreads();
    }
    if (threadIdx.x == 0) {
        // mean over Q of (codebook_loss + 0.25*commit_loss) = 1.25 * sum / (Q*N*D)
        out[(size_t)NN * DD] = (float)(sh[0] * 1.25 / ((double)QQ * NN * DD));
    }
}

extern "C" void kernel_launch(void* const* d_in, const int* in_sizes, int n_in,
                              void* d_out, int out_size)
{
    const float* x  = (const float*)d_in[0];
    const float* cb = (const float*)d_in[1];
    float* out = (float*)d_out;
    size_t smem = (size_t)KK * DD * sizeof(u64)   // negated-dup codebook
                + (size_t)KK * sizeof(u64)        // (ee/2, ee/2)
                + (size_t)KK * sizeof(float);     // raw ee
    cudaFuncSetAttribute(rvq_kernel, cudaFuncAttributeMaxDynamicSharedMemorySize, (int)smem);
    rvq_kernel<<<GRID, THREADS, smem>>>(x, cb, out);
    rvq_finalize<<<1, 256>>>(out);
}